// round 1
// baseline (speedup 1.0000x reference)
#include <cuda_runtime.h>
#include <cuda_bf16.h>
#include <cstdint>

#define N_NODES 100000
#define N_EDGES 1200000
#define D 64

// Scratch for f1/f2 aggregation: [2][N_NODES*64] floats = 51.2 MB.
// __device__ global (allocation-free per harness rules).
__device__ float g_f[2 * N_NODES * D];

// ---------------------------------------------------------------------------
// Edge stage: 16 lanes per edge. Each lane handles one float4 chunk (4 cols).
// Gather x[src], x[dst] (coalesced 256B row reads, L2-resident),
// scatter-add m1/m2 into f1/f2 via vector red.global.add.v4.f32.
// ---------------------------------------------------------------------------
__device__ __forceinline__ void red_add_v4(float* p, float4 v) {
    asm volatile(
        "red.global.add.v4.f32 [%0], {%1, %2, %3, %4};"
        :: "l"(__cvta_generic_to_global(p)),
           "f"(v.x), "f"(v.y), "f"(v.z), "f"(v.w)
        : "memory");
}

__global__ void __launch_bounds__(256) edge_kernel(
    const float* __restrict__ x,
    const float* __restrict__ norm,
    const int* __restrict__ src,
    const int* __restrict__ dst,
    float* __restrict__ f1,
    float* __restrict__ f2)
{
    int tid = blockIdx.x * blockDim.x + threadIdx.x;
    int e  = tid >> 4;        // edge index
    int le = tid & 15;        // lane-within-edge: float4 chunk id
    if (e >= N_EDGES) return;

    int s = __ldg(src + e);
    int d = __ldg(dst + e);
    float coef = __ldg(norm + s) * __ldg(norm + d);

    const float4* x4 = reinterpret_cast<const float4*>(x);
    float4 vs = __ldg(x4 + s * 16 + le);
    float4 vd = __ldg(x4 + d * 16 + le);

    float4 m1, m2;
    m1.x = vs.x * coef;  m1.y = vs.y * coef;  m1.z = vs.z * coef;  m1.w = vs.w * coef;
    m2.x = vs.x * vd.x * coef;
    m2.y = vs.y * vd.y * coef;
    m2.z = vs.z * vd.z * coef;
    m2.w = vs.w * vd.w * coef;

    int off = d * D + le * 4;
    red_add_v4(f1 + off, m1);
    red_add_v4(f2 + off, m2);
}

// ---------------------------------------------------------------------------
// Epilogue GEMM: out[n, :] = f1[n,:] @ W1 + f2[n,:] @ W2 + b1 + b2
// 64 nodes per block, 256 threads. Thread (cg, ns) computes cols [cg*4, cg*4+4)
// for 4 nodes {ns*4 .. ns*4+3}. W1/W2 + f tiles staged in dynamic shared.
// f tiles padded to 65 floats/row to avoid bank conflicts.
// ---------------------------------------------------------------------------
#define GEMM_NODES 64
#define FPAD 65

__global__ void __launch_bounds__(256) gemm_kernel(
    const float* __restrict__ f1,
    const float* __restrict__ f2,
    const float* __restrict__ W1,
    const float* __restrict__ b1,
    const float* __restrict__ W2,
    const float* __restrict__ b2,
    float* __restrict__ out)
{
    extern __shared__ float sh[];
    float* W1s = sh;                       // 64*64
    float* W2s = W1s + D * D;              // 64*64
    float* f1s = W2s + D * D;              // 64*65
    float* f2s = f1s + GEMM_NODES * FPAD;  // 64*65

    int t = threadIdx.x;
    int node0 = blockIdx.x * GEMM_NODES;

    // Load W1/W2 into shared (coalesced)
    #pragma unroll
    for (int i = 0; i < (D * D) / 256; i++) {
        int idx = i * 256 + t;
        W1s[idx] = __ldg(W1 + idx);
        W2s[idx] = __ldg(W2 + idx);
    }

    // Load f1/f2 tiles (64 rows x 64 cols) into padded shared
    #pragma unroll
    for (int i = 0; i < (GEMM_NODES * D) / 256; i++) {
        int idx = i * 256 + t;
        int row = idx >> 6;
        int col = idx & 63;
        int node = node0 + row;
        float v1 = 0.f, v2 = 0.f;
        if (node < N_NODES) {
            v1 = f1[node * D + col];
            v2 = f2[node * D + col];
        }
        f1s[row * FPAD + col] = v1;
        f2s[row * FPAD + col] = v2;
    }
    __syncthreads();

    int cg = t & 15;          // column group
    int c0 = cg * 4;
    int ns = t >> 4;          // node slot: owns nodes ns*4 .. ns*4+3

    float4 acc[4];
    #pragma unroll
    for (int i = 0; i < 4; i++) acc[i] = make_float4(0.f, 0.f, 0.f, 0.f);

    #pragma unroll 4
    for (int k = 0; k < D; k++) {
        float4 w1 = *reinterpret_cast<const float4*>(&W1s[k * D + c0]);
        float4 w2 = *reinterpret_cast<const float4*>(&W2s[k * D + c0]);
        #pragma unroll
        for (int i = 0; i < 4; i++) {
            float a1 = f1s[(ns * 4 + i) * FPAD + k];
            float a2 = f2s[(ns * 4 + i) * FPAD + k];
            acc[i].x = fmaf(a1, w1.x, fmaf(a2, w2.x, acc[i].x));
            acc[i].y = fmaf(a1, w1.y, fmaf(a2, w2.y, acc[i].y));
            acc[i].z = fmaf(a1, w1.z, fmaf(a2, w2.z, acc[i].z));
            acc[i].w = fmaf(a1, w1.w, fmaf(a2, w2.w, acc[i].w));
        }
    }

    float4 bb1 = __ldg(reinterpret_cast<const float4*>(b1) + cg);
    float4 bb2 = __ldg(reinterpret_cast<const float4*>(b2) + cg);
    float4 bias = make_float4(bb1.x + bb2.x, bb1.y + bb2.y,
                              bb1.z + bb2.z, bb1.w + bb2.w);

    #pragma unroll
    for (int i = 0; i < 4; i++) {
        int node = node0 + ns * 4 + i;
        if (node < N_NODES) {
            float4 r = make_float4(acc[i].x + bias.x, acc[i].y + bias.y,
                                   acc[i].z + bias.z, acc[i].w + bias.w);
            *reinterpret_cast<float4*>(&out[node * D + c0]) = r;
        }
    }
}

// ---------------------------------------------------------------------------
// Launch
// ---------------------------------------------------------------------------
extern "C" void kernel_launch(void* const* d_in, const int* in_sizes, int n_in,
                              void* d_out, int out_size)
{
    const float* x    = (const float*)d_in[0];
    const float* norm = (const float*)d_in[1];
    const int*   src  = (const int*)  d_in[2];
    const int*   dst  = (const int*)  d_in[3];
    const float* W1   = (const float*)d_in[4];
    const float* b1   = (const float*)d_in[5];
    const float* W2   = (const float*)d_in[6];
    const float* b2   = (const float*)d_in[7];
    float* out = (float*)d_out;

    float* f;
    cudaGetSymbolAddress((void**)&f, g_f);
    float* f1 = f;
    float* f2 = f + (size_t)N_NODES * D;

    // Zero the aggregation scratch (graph-capturable memset)
    cudaMemsetAsync(f, 0, sizeof(float) * 2 * N_NODES * D);

    // Edge stage: 16 lanes per edge
    {
        long long threads = (long long)N_EDGES * 16;
        int block = 256;
        int grid = (int)((threads + block - 1) / block);
        edge_kernel<<<grid, block>>>(x, norm, src, dst, f1, f2);
    }

    // Epilogue GEMM
    {
        size_t shmem = sizeof(float) * (2 * D * D + 2 * GEMM_NODES * FPAD);
        cudaFuncSetAttribute(gemm_kernel,
                             cudaFuncAttributeMaxDynamicSharedMemorySize,
                             (int)shmem);
        int grid = (N_NODES + GEMM_NODES - 1) / GEMM_NODES;
        gemm_kernel<<<grid, 256, shmem>>>(f1, f2, W1, b1, W2, b2, out);
    }
}

// round 2
// speedup vs baseline: 1.2597x; 1.2597x over previous
#include <cuda_runtime.h>
#include <cuda_bf16.h>
#include <cstdint>

#define N_NODES 100000
#define N_EDGES 1200000
#define D 64
#define SCAN_B 1024
#define NBLK ((N_NODES + SCAN_B - 1) / SCAN_B)   // 98
#define GEMM_NODES 64
#define FPAD 66

// ---- CSR build scratch (allocation-free __device__ globals, ~10.4 MB) ----
__device__ int  g_count[N_NODES];
__device__ int  g_off[N_NODES + 1];
__device__ int  g_cursor[N_NODES];
__device__ int  g_bsums[128];
__device__ int2 g_edge[N_EDGES];     // packed {src, __float_as_int(coef)}

// ---------------------------------------------------------------------------
// CSR build kernels
// ---------------------------------------------------------------------------
__global__ void __launch_bounds__(256) hist_kernel(const int* __restrict__ dst)
{
    int e = blockIdx.x * blockDim.x + threadIdx.x;
    if (e < N_EDGES) atomicAdd(&g_count[dst[e]], 1);
}

__global__ void __launch_bounds__(SCAN_B) scan_part_kernel()
{
    __shared__ int sh[SCAN_B];
    int i = blockIdx.x * SCAN_B + threadIdx.x;
    int v = (i < N_NODES) ? g_count[i] : 0;
    sh[threadIdx.x] = v;
    __syncthreads();
    #pragma unroll
    for (int d = 1; d < SCAN_B; d <<= 1) {
        int t = (threadIdx.x >= d) ? sh[threadIdx.x - d] : 0;
        __syncthreads();
        sh[threadIdx.x] += t;
        __syncthreads();
    }
    if (i < N_NODES) g_off[i] = sh[threadIdx.x] - v;   // exclusive within block
    if (threadIdx.x == SCAN_B - 1) g_bsums[blockIdx.x] = sh[SCAN_B - 1];
}

__global__ void __launch_bounds__(128) scan_top_kernel()
{
    __shared__ int sh[128];
    int t = threadIdx.x;
    int v = (t < NBLK) ? g_bsums[t] : 0;
    sh[t] = v;
    __syncthreads();
    #pragma unroll
    for (int d = 1; d < 128; d <<= 1) {
        int u = (t >= d) ? sh[t - d] : 0;
        __syncthreads();
        sh[t] += u;
        __syncthreads();
    }
    if (t < NBLK) g_bsums[t] = sh[t] - v;              // exclusive block offsets
}

__global__ void __launch_bounds__(256) scan_add_kernel()
{
    int i = blockIdx.x * blockDim.x + threadIdx.x;
    if (i < N_NODES) {
        int o = g_off[i] + g_bsums[i >> 10];
        g_off[i] = o;
        g_cursor[i] = o;
    }
    if (i == 0) g_off[N_NODES] = N_EDGES;
}

__global__ void __launch_bounds__(256) scatter_kernel(
    const int* __restrict__ src, const int* __restrict__ dst,
    const float* __restrict__ norm)
{
    int e = blockIdx.x * blockDim.x + threadIdx.x;
    if (e >= N_EDGES) return;
    int s = src[e], d = dst[e];
    float c = __ldg(norm + s) * __ldg(norm + d);
    int pos = atomicAdd(&g_cursor[d], 1);
    g_edge[pos] = make_int2(s, __float_as_int(c));
}

// ---------------------------------------------------------------------------
// Fused aggregate + dual-GEMM kernel.
// 64 nodes/block, 256 threads (8 warps).
// Phase B: warp w aggregates nodes w*8..w*8+7 straight into shared f tiles.
//          Each lane owns a float2 column pair; x[dst] row cached in regs;
//          per edge only x[src] (256B coalesced gather) + 8B packed index.
// Phase C: register-blocked FFMA gemm: out = f1@W1 + f2@W2 + b1 + b2.
// ---------------------------------------------------------------------------
__global__ void __launch_bounds__(256) fused_kernel(
    const float* __restrict__ x,
    const float* __restrict__ W1, const float* __restrict__ b1,
    const float* __restrict__ W2, const float* __restrict__ b2,
    float* __restrict__ out)
{
    extern __shared__ float sh[];
    float* W1s = sh;                        // 64*64
    float* W2s = W1s + D * D;               // 64*64
    float* f1s = W2s + D * D;               // 64*66
    float* f2s = f1s + GEMM_NODES * FPAD;   // 64*66

    int t = threadIdx.x;
    int node0 = blockIdx.x * GEMM_NODES;

    // Load weights
    #pragma unroll
    for (int i = 0; i < (D * D) / 256; i++) {
        int idx = i * 256 + t;
        W1s[idx] = __ldg(W1 + idx);
        W2s[idx] = __ldg(W2 + idx);
    }

    // ---- Phase B: CSR aggregation into shared ----
    int w = t >> 5, lane = t & 31;
    const float2* x2 = reinterpret_cast<const float2*>(x);

    #pragma unroll 1
    for (int j = 0; j < 8; j++) {
        int row = w * 8 + j;
        int n = node0 + row;
        float2 a1 = make_float2(0.f, 0.f);
        float2 a2 = make_float2(0.f, 0.f);
        if (n < N_NODES) {
            float2 vd = __ldg(&x2[n * 32 + lane]);
            int beg = __ldg(g_off + n);
            int end = __ldg(g_off + n + 1);
            for (int e = beg; e < end; e++) {
                int2 ec = __ldg(&g_edge[e]);
                float c = __int_as_float(ec.y);
                float2 vs = __ldg(&x2[ec.x * 32 + lane]);
                a1.x = fmaf(vs.x, c, a1.x);
                a1.y = fmaf(vs.y, c, a1.y);
                a2.x = fmaf(vs.x * vd.x, c, a2.x);
                a2.y = fmaf(vs.y * vd.y, c, a2.y);
            }
        }
        *reinterpret_cast<float2*>(&f1s[row * FPAD + 2 * lane]) = a1;
        *reinterpret_cast<float2*>(&f2s[row * FPAD + 2 * lane]) = a2;
    }
    __syncthreads();

    // ---- Phase C: dual GEMM ----
    int cg = t & 15;          // column group (4 cols)
    int c0 = cg * 4;
    int ns = t >> 4;          // node slot: nodes ns*4 .. ns*4+3

    float4 acc[4];
    #pragma unroll
    for (int i = 0; i < 4; i++) acc[i] = make_float4(0.f, 0.f, 0.f, 0.f);

    #pragma unroll 4
    for (int k = 0; k < D; k++) {
        float4 w1 = *reinterpret_cast<const float4*>(&W1s[k * D + c0]);
        float4 w2 = *reinterpret_cast<const float4*>(&W2s[k * D + c0]);
        #pragma unroll
        for (int i = 0; i < 4; i++) {
            float a1 = f1s[(ns * 4 + i) * FPAD + k];
            float a2 = f2s[(ns * 4 + i) * FPAD + k];
            acc[i].x = fmaf(a1, w1.x, fmaf(a2, w2.x, acc[i].x));
            acc[i].y = fmaf(a1, w1.y, fmaf(a2, w2.y, acc[i].y));
            acc[i].z = fmaf(a1, w1.z, fmaf(a2, w2.z, acc[i].z));
            acc[i].w = fmaf(a1, w1.w, fmaf(a2, w2.w, acc[i].w));
        }
    }

    float4 bb1 = __ldg(reinterpret_cast<const float4*>(b1) + cg);
    float4 bb2 = __ldg(reinterpret_cast<const float4*>(b2) + cg);
    float4 bias = make_float4(bb1.x + bb2.x, bb1.y + bb2.y,
                              bb1.z + bb2.z, bb1.w + bb2.w);

    #pragma unroll
    for (int i = 0; i < 4; i++) {
        int node = node0 + ns * 4 + i;
        if (node < N_NODES) {
            float4 r = make_float4(acc[i].x + bias.x, acc[i].y + bias.y,
                                   acc[i].z + bias.z, acc[i].w + bias.w);
            *reinterpret_cast<float4*>(&out[node * D + c0]) = r;
        }
    }
}

// ---------------------------------------------------------------------------
// Launch
// ---------------------------------------------------------------------------
extern "C" void kernel_launch(void* const* d_in, const int* in_sizes, int n_in,
                              void* d_out, int out_size)
{
    const float* x    = (const float*)d_in[0];
    const float* norm = (const float*)d_in[1];
    const int*   src  = (const int*)  d_in[2];
    const int*   dst  = (const int*)  d_in[3];
    const float* W1   = (const float*)d_in[4];
    const float* b1   = (const float*)d_in[5];
    const float* W2   = (const float*)d_in[6];
    const float* b2   = (const float*)d_in[7];
    float* out = (float*)d_out;

    void* count_ptr;
    cudaGetSymbolAddress(&count_ptr, g_count);
    cudaMemsetAsync(count_ptr, 0, sizeof(int) * N_NODES);

    int eblocks = (N_EDGES + 255) / 256;
    hist_kernel<<<eblocks, 256>>>(dst);
    scan_part_kernel<<<NBLK, SCAN_B>>>();
    scan_top_kernel<<<1, 128>>>();
    scan_add_kernel<<<(N_NODES + 255) / 256, 256>>>();
    scatter_kernel<<<eblocks, 256>>>(src, dst, norm);

    size_t shmem = sizeof(float) * (2 * D * D + 2 * GEMM_NODES * FPAD);
    cudaFuncSetAttribute(fused_kernel,
                         cudaFuncAttributeMaxDynamicSharedMemorySize,
                         (int)shmem);
    int grid = (N_NODES + GEMM_NODES - 1) / GEMM_NODES;
    fused_kernel<<<grid, 256, shmem>>>(x, W1, b1, W2, b2, out);
}

// round 3
// speedup vs baseline: 1.3747x; 1.0913x over previous
#include <cuda_runtime.h>
#include <cuda_bf16.h>
#include <cstdint>

#define N_NODES 100000
#define N_EDGES 1200000
#define D 64
#define CAP 64                 // max in-degree capacity (Poisson(12): P(>=64) ~ 5e-26)
#define GEMM_NODES 64
#define FPAD 68                // padded f row: mult of 4 (16B aligned), bank offset 4/row

// ---- scratch (__device__ globals, allocation-free) ----
__device__ int  g_count[N_NODES];
__device__ int2 g_edge[(size_t)N_NODES * CAP];   // {src, __float_as_int(coef)}

// ---------------------------------------------------------------------------
// Build: single scatter pass into fixed-capacity buckets.
// ---------------------------------------------------------------------------
__global__ void __launch_bounds__(256) scatter_kernel(
    const int* __restrict__ src, const int* __restrict__ dst,
    const float* __restrict__ norm)
{
    int e = blockIdx.x * blockDim.x + threadIdx.x;
    if (e >= N_EDGES) return;
    int s = src[e], d = dst[e];
    float c = __ldg(norm + s) * __ldg(norm + d);
    int pos = atomicAdd(&g_count[d], 1);
    g_edge[(size_t)d * CAP + pos] = make_int2(s, __float_as_int(c));
}

// ---------------------------------------------------------------------------
// Fused aggregate + dual-GEMM.
// Phase B: warp-per-node. Lanes 0-15 / 16-31 form two half-warps, each
//          covering the 64-col row with float4 chunks, striding the edge
//          list by 2 (x2 unroll -> 4 edges in flight). Halves combined by
//          shfl, result written to shared f tiles.
// Phase C: out = f1@W1 + f2@W2 + b1 + b2, k blocked by 4 with LDS.128 loads.
// ---------------------------------------------------------------------------
__global__ void __launch_bounds__(256) fused_kernel(
    const float* __restrict__ x,
    const float* __restrict__ W1, const float* __restrict__ b1,
    const float* __restrict__ W2, const float* __restrict__ b2,
    float* __restrict__ out)
{
    extern __shared__ float sh[];
    float* W1s = sh;                        // 64*64
    float* W2s = W1s + D * D;               // 64*64
    float* f1s = W2s + D * D;               // 64*68
    float* f2s = f1s + GEMM_NODES * FPAD;   // 64*68

    int t = threadIdx.x;
    int node0 = blockIdx.x * GEMM_NODES;

    // Load weights into shared (coalesced)
    #pragma unroll
    for (int i = 0; i < (D * D) / 256; i++) {
        int idx = i * 256 + t;
        W1s[idx] = __ldg(W1 + idx);
        W2s[idx] = __ldg(W2 + idx);
    }

    // ---- Phase B: aggregation ----
    int w = t >> 5, lane = t & 31;
    int half = lane >> 4;         // 0 or 1
    int le = lane & 15;           // float4 chunk within the 64-col row
    const float4* x4 = reinterpret_cast<const float4*>(x);

    #pragma unroll 1
    for (int j = 0; j < 8; j++) {
        int row = w * 8 + j;
        int n = node0 + row;
        float4 a1 = make_float4(0.f, 0.f, 0.f, 0.f);
        float4 a2 = make_float4(0.f, 0.f, 0.f, 0.f);
        if (n < N_NODES) {
            float4 vd = __ldg(x4 + n * 16 + le);
            int cnt = __ldg(g_count + n);
            const int2* ep = g_edge + (size_t)n * CAP;
            int e = half;
            // 2-edge unroll per half-warp: 4 edges in flight per warp
            for (; e + 2 < cnt; e += 4) {
                int2 ea = __ldg(ep + e);
                int2 eb = __ldg(ep + e + 2);
                float ca = __int_as_float(ea.y);
                float cb = __int_as_float(eb.y);
                float4 va = __ldg(x4 + ea.x * 16 + le);
                float4 vb = __ldg(x4 + eb.x * 16 + le);
                a1.x = fmaf(va.x, ca, a1.x); a1.y = fmaf(va.y, ca, a1.y);
                a1.z = fmaf(va.z, ca, a1.z); a1.w = fmaf(va.w, ca, a1.w);
                a2.x = fmaf(va.x * vd.x, ca, a2.x); a2.y = fmaf(va.y * vd.y, ca, a2.y);
                a2.z = fmaf(va.z * vd.z, ca, a2.z); a2.w = fmaf(va.w * vd.w, ca, a2.w);
                a1.x = fmaf(vb.x, cb, a1.x); a1.y = fmaf(vb.y, cb, a1.y);
                a1.z = fmaf(vb.z, cb, a1.z); a1.w = fmaf(vb.w, cb, a1.w);
                a2.x = fmaf(vb.x * vd.x, cb, a2.x); a2.y = fmaf(vb.y * vd.y, cb, a2.y);
                a2.z = fmaf(vb.z * vd.z, cb, a2.z); a2.w = fmaf(vb.w * vd.w, cb, a2.w);
            }
            if (e < cnt) {
                int2 ea = __ldg(ep + e);
                float ca = __int_as_float(ea.y);
                float4 va = __ldg(x4 + ea.x * 16 + le);
                a1.x = fmaf(va.x, ca, a1.x); a1.y = fmaf(va.y, ca, a1.y);
                a1.z = fmaf(va.z, ca, a1.z); a1.w = fmaf(va.w, ca, a1.w);
                a2.x = fmaf(va.x * vd.x, ca, a2.x); a2.y = fmaf(va.y * vd.y, ca, a2.y);
                a2.z = fmaf(va.z * vd.z, ca, a2.z); a2.w = fmaf(va.w * vd.w, ca, a2.w);
            }
        }
        // combine halves (half1 -> half0)
        a1.x += __shfl_down_sync(0xffffffffu, a1.x, 16);
        a1.y += __shfl_down_sync(0xffffffffu, a1.y, 16);
        a1.z += __shfl_down_sync(0xffffffffu, a1.z, 16);
        a1.w += __shfl_down_sync(0xffffffffu, a1.w, 16);
        a2.x += __shfl_down_sync(0xffffffffu, a2.x, 16);
        a2.y += __shfl_down_sync(0xffffffffu, a2.y, 16);
        a2.z += __shfl_down_sync(0xffffffffu, a2.z, 16);
        a2.w += __shfl_down_sync(0xffffffffu, a2.w, 16);
        if (half == 0) {
            *reinterpret_cast<float4*>(&f1s[row * FPAD + 4 * le]) = a1;
            *reinterpret_cast<float4*>(&f2s[row * FPAD + 4 * le]) = a2;
        }
    }
    __syncthreads();

    // ---- Phase C: dual GEMM, k blocked by 4 ----
    int cg = t & 15;
    int c0 = cg * 4;
    int ns = t >> 4;

    float4 acc[4];
    #pragma unroll
    for (int i = 0; i < 4; i++) acc[i] = make_float4(0.f, 0.f, 0.f, 0.f);

    #pragma unroll
    for (int k4 = 0; k4 < D; k4 += 4) {
        float4 fa[4], fb[4];
        #pragma unroll
        for (int i = 0; i < 4; i++) {
            fa[i] = *reinterpret_cast<const float4*>(&f1s[(ns * 4 + i) * FPAD + k4]);
            fb[i] = *reinterpret_cast<const float4*>(&f2s[(ns * 4 + i) * FPAD + k4]);
        }
        #pragma unroll
        for (int kk = 0; kk < 4; kk++) {
            float4 w1 = *reinterpret_cast<const float4*>(&W1s[(k4 + kk) * D + c0]);
            float4 w2 = *reinterpret_cast<const float4*>(&W2s[(k4 + kk) * D + c0]);
            #pragma unroll
            for (int i = 0; i < 4; i++) {
                float a1 = (&fa[i].x)[kk];
                float a2 = (&fb[i].x)[kk];
                acc[i].x = fmaf(a1, w1.x, fmaf(a2, w2.x, acc[i].x));
                acc[i].y = fmaf(a1, w1.y, fmaf(a2, w2.y, acc[i].y));
                acc[i].z = fmaf(a1, w1.z, fmaf(a2, w2.z, acc[i].z));
                acc[i].w = fmaf(a1, w1.w, fmaf(a2, w2.w, acc[i].w));
            }
        }
    }

    float4 bb1 = __ldg(reinterpret_cast<const float4*>(b1) + cg);
    float4 bb2 = __ldg(reinterpret_cast<const float4*>(b2) + cg);
    float4 bias = make_float4(bb1.x + bb2.x, bb1.y + bb2.y,
                              bb1.z + bb2.z, bb1.w + bb2.w);

    #pragma unroll
    for (int i = 0; i < 4; i++) {
        int node = node0 + ns * 4 + i;
        if (node < N_NODES) {
            float4 r = make_float4(acc[i].x + bias.x, acc[i].y + bias.y,
                                   acc[i].z + bias.z, acc[i].w + bias.w);
            *reinterpret_cast<float4*>(&out[node * D + c0]) = r;
        }
    }
}

// ---------------------------------------------------------------------------
// Launch
// ---------------------------------------------------------------------------
extern "C" void kernel_launch(void* const* d_in, const int* in_sizes, int n_in,
                              void* d_out, int out_size)
{
    const float* x    = (const float*)d_in[0];
    const float* norm = (const float*)d_in[1];
    const int*   src  = (const int*)  d_in[2];
    const int*   dst  = (const int*)  d_in[3];
    const float* W1   = (const float*)d_in[4];
    const float* b1   = (const float*)d_in[5];
    const float* W2   = (const float*)d_in[6];
    const float* b2   = (const float*)d_in[7];
    float* out = (float*)d_out;

    void* count_ptr;
    cudaGetSymbolAddress(&count_ptr, g_count);
    cudaMemsetAsync(count_ptr, 0, sizeof(int) * N_NODES);

    int eblocks = (N_EDGES + 255) / 256;
    scatter_kernel<<<eblocks, 256>>>(src, dst, norm);

    size_t shmem = sizeof(float) * (2 * D * D + 2 * GEMM_NODES * FPAD);
    cudaFuncSetAttribute(fused_kernel,
                         cudaFuncAttributeMaxDynamicSharedMemorySize,
                         (int)shmem);
    int grid = (N_NODES + GEMM_NODES - 1) / GEMM_NODES;
    fused_kernel<<<grid, 256, shmem>>>(x, W1, b1, W2, b2, out);
}

// round 4
// speedup vs baseline: 1.4636x; 1.0647x over previous
#include <cuda_runtime.h>
#include <cuda_bf16.h>
#include <cstdint>

#define N_NODES 100000
#define N_EDGES 1200000
#define D 64
#define CAP 64                 // max in-degree capacity (Poisson(12): P(>=64) ~ 5e-26)
#define GEMM_NODES 32          // nodes per block
#define FPAD 68                // padded f row: mult of 4 (16B aligned), bank spread

// ---- scratch (__device__ globals, allocation-free) ----
__device__ int  g_count[N_NODES];
__device__ int2 g_edge[(size_t)N_NODES * CAP];   // {src, __float_as_int(coef)}

// ---------------------------------------------------------------------------
// Build: single scatter pass into fixed-capacity buckets.
// ---------------------------------------------------------------------------
__global__ void __launch_bounds__(256) scatter_kernel(
    const int* __restrict__ src, const int* __restrict__ dst,
    const float* __restrict__ norm)
{
    int e = blockIdx.x * blockDim.x + threadIdx.x;
    if (e >= N_EDGES) return;
    int s = src[e], d = dst[e];
    float c = __ldg(norm + s) * __ldg(norm + d);
    int pos = atomicAdd(&g_count[d], 1);
    g_edge[(size_t)d * CAP + pos] = make_int2(s, __float_as_int(c));
}

// ---------------------------------------------------------------------------
// Fused aggregate + dual-GEMM. 128 threads (4 warps), 32 nodes per block.
// Phase B: warp-per-node (8 nodes/warp). Two half-warps each cover the
//          64-col row with float4 lanes, striding edges by 2 with x2 unroll
//          (4 edges in flight per warp); shfl-combine; write shared f tiles.
// Phase C: out = f1@W1 + f2@W2 + b1 + b2. f from shared (LDS.128,
//          broadcast), W via __ldg (L1-resident, warp-uniform addresses).
// ---------------------------------------------------------------------------
__global__ void __launch_bounds__(128, 8) fused_kernel(
    const float* __restrict__ x,
    const float* __restrict__ W1, const float* __restrict__ b1,
    const float* __restrict__ W2, const float* __restrict__ b2,
    float* __restrict__ out)
{
    extern __shared__ float sh[];
    float* f1s = sh;                        // 32*68
    float* f2s = f1s + GEMM_NODES * FPAD;   // 32*68

    int t = threadIdx.x;
    int node0 = blockIdx.x * GEMM_NODES;

    // ---- Phase B: aggregation ----
    int w = t >> 5, lane = t & 31;
    int half = lane >> 4;         // 0 or 1
    int le = lane & 15;           // float4 chunk within 64-col row
    const float4* x4 = reinterpret_cast<const float4*>(x);

    #pragma unroll 1
    for (int j = 0; j < 8; j++) {
        int row = w * 8 + j;
        int n = node0 + row;
        float4 a1 = make_float4(0.f, 0.f, 0.f, 0.f);
        float4 a2 = make_float4(0.f, 0.f, 0.f, 0.f);
        if (n < N_NODES) {
            float4 vd = __ldg(x4 + n * 16 + le);
            int cnt = __ldg(g_count + n);
            const int2* ep = g_edge + (size_t)n * CAP;
            int e = half;
            for (; e + 2 < cnt; e += 4) {
                int2 ea = __ldg(ep + e);
                int2 eb = __ldg(ep + e + 2);
                float ca = __int_as_float(ea.y);
                float cb = __int_as_float(eb.y);
                float4 va = __ldg(x4 + ea.x * 16 + le);
                float4 vb = __ldg(x4 + eb.x * 16 + le);
                a1.x = fmaf(va.x, ca, a1.x); a1.y = fmaf(va.y, ca, a1.y);
                a1.z = fmaf(va.z, ca, a1.z); a1.w = fmaf(va.w, ca, a1.w);
                a2.x = fmaf(va.x * vd.x, ca, a2.x); a2.y = fmaf(va.y * vd.y, ca, a2.y);
                a2.z = fmaf(va.z * vd.z, ca, a2.z); a2.w = fmaf(va.w * vd.w, ca, a2.w);
                a1.x = fmaf(vb.x, cb, a1.x); a1.y = fmaf(vb.y, cb, a1.y);
                a1.z = fmaf(vb.z, cb, a1.z); a1.w = fmaf(vb.w, cb, a1.w);
                a2.x = fmaf(vb.x * vd.x, cb, a2.x); a2.y = fmaf(vb.y * vd.y, cb, a2.y);
                a2.z = fmaf(vb.z * vd.z, cb, a2.z); a2.w = fmaf(vb.w * vd.w, cb, a2.w);
            }
            if (e < cnt) {
                int2 ea = __ldg(ep + e);
                float ca = __int_as_float(ea.y);
                float4 va = __ldg(x4 + ea.x * 16 + le);
                a1.x = fmaf(va.x, ca, a1.x); a1.y = fmaf(va.y, ca, a1.y);
                a1.z = fmaf(va.z, ca, a1.z); a1.w = fmaf(va.w, ca, a1.w);
                a2.x = fmaf(va.x * vd.x, ca, a2.x); a2.y = fmaf(va.y * vd.y, ca, a2.y);
                a2.z = fmaf(va.z * vd.z, ca, a2.z); a2.w = fmaf(va.w * vd.w, ca, a2.w);
            }
        }
        // combine halves (half1 -> half0)
        a1.x += __shfl_down_sync(0xffffffffu, a1.x, 16);
        a1.y += __shfl_down_sync(0xffffffffu, a1.y, 16);
        a1.z += __shfl_down_sync(0xffffffffu, a1.z, 16);
        a1.w += __shfl_down_sync(0xffffffffu, a1.w, 16);
        a2.x += __shfl_down_sync(0xffffffffu, a2.x, 16);
        a2.y += __shfl_down_sync(0xffffffffu, a2.y, 16);
        a2.z += __shfl_down_sync(0xffffffffu, a2.z, 16);
        a2.w += __shfl_down_sync(0xffffffffu, a2.w, 16);
        if (half == 0) {
            *reinterpret_cast<float4*>(&f1s[row * FPAD + 4 * le]) = a1;
            *reinterpret_cast<float4*>(&f2s[row * FPAD + 4 * le]) = a2;
        }
    }
    __syncthreads();

    // ---- Phase C: dual GEMM, k blocked by 4, W from L1 via __ldg ----
    int cg = t & 15;
    int c0 = cg * 4;
    int ns = t >> 4;              // 0..7, each owns nodes ns*4..ns*4+3

    const float4* W1v = reinterpret_cast<const float4*>(W1);
    const float4* W2v = reinterpret_cast<const float4*>(W2);

    float4 acc[4];
    #pragma unroll
    for (int i = 0; i < 4; i++) acc[i] = make_float4(0.f, 0.f, 0.f, 0.f);

    #pragma unroll 4
    for (int k4 = 0; k4 < D; k4 += 4) {
        float4 fa[4], fb[4];
        #pragma unroll
        for (int i = 0; i < 4; i++) {
            fa[i] = *reinterpret_cast<const float4*>(&f1s[(ns * 4 + i) * FPAD + k4]);
            fb[i] = *reinterpret_cast<const float4*>(&f2s[(ns * 4 + i) * FPAD + k4]);
        }
        #pragma unroll
        for (int kk = 0; kk < 4; kk++) {
            float4 w1 = __ldg(W1v + (k4 + kk) * 16 + cg);
            float4 w2 = __ldg(W2v + (k4 + kk) * 16 + cg);
            #pragma unroll
            for (int i = 0; i < 4; i++) {
                float a1 = (&fa[i].x)[kk];
                float a2 = (&fb[i].x)[kk];
                acc[i].x = fmaf(a1, w1.x, fmaf(a2, w2.x, acc[i].x));
                acc[i].y = fmaf(a1, w1.y, fmaf(a2, w2.y, acc[i].y));
                acc[i].z = fmaf(a1, w1.z, fmaf(a2, w2.z, acc[i].z));
                acc[i].w = fmaf(a1, w1.w, fmaf(a2, w2.w, acc[i].w));
            }
        }
    }

    float4 bb1 = __ldg(reinterpret_cast<const float4*>(b1) + cg);
    float4 bb2 = __ldg(reinterpret_cast<const float4*>(b2) + cg);
    float4 bias = make_float4(bb1.x + bb2.x, bb1.y + bb2.y,
                              bb1.z + bb2.z, bb1.w + bb2.w);

    #pragma unroll
    for (int i = 0; i < 4; i++) {
        int node = node0 + ns * 4 + i;
        if (node < N_NODES) {
            float4 r = make_float4(acc[i].x + bias.x, acc[i].y + bias.y,
                                   acc[i].z + bias.z, acc[i].w + bias.w);
            *reinterpret_cast<float4*>(&out[node * D + c0]) = r;
        }
    }
}

// ---------------------------------------------------------------------------
// Launch
// ---------------------------------------------------------------------------
extern "C" void kernel_launch(void* const* d_in, const int* in_sizes, int n_in,
                              void* d_out, int out_size)
{
    const float* x    = (const float*)d_in[0];
    const float* norm = (const float*)d_in[1];
    const int*   src  = (const int*)  d_in[2];
    const int*   dst  = (const int*)  d_in[3];
    const float* W1   = (const float*)d_in[4];
    const float* b1   = (const float*)d_in[5];
    const float* W2   = (const float*)d_in[6];
    const float* b2   = (const float*)d_in[7];
    float* out = (float*)d_out;

    void* count_ptr;
    cudaGetSymbolAddress(&count_ptr, g_count);
    cudaMemsetAsync(count_ptr, 0, sizeof(int) * N_NODES);

    int eblocks = (N_EDGES + 255) / 256;
    scatter_kernel<<<eblocks, 256>>>(src, dst, norm);

    size_t shmem = sizeof(float) * (2 * GEMM_NODES * FPAD);
    cudaFuncSetAttribute(fused_kernel,
                         cudaFuncAttributeMaxDynamicSharedMemorySize,
                         (int)shmem);
    int grid = (N_NODES + GEMM_NODES - 1) / GEMM_NODES;
    fused_kernel<<<grid, 128, shmem>>>(x, W1, b1, W2, b2, out);
}